// round 3
// baseline (speedup 1.0000x reference)
#include <cuda_runtime.h>
#include <stdint.h>

#define BATCH     128
#define SIG_SIZE  299592
#define HSIZE     37448          // levels 1..5 of Horner state, per batch
#define NOUT      51360          // number of Lyndon words, c=8, depth<=6
#define NBLK_LYN  76             // 4 (lvls 1-4) + 8 (lvl5) + 64 (lvl6), 4096 words/block

// Level offsets within a signature row: OFF[k] = (8^k - 8)/7
__constant__ int d_OFF[7] = {0, 0, 8, 72, 584, 4680, 37448};

// Scratch (static device memory only — no allocations allowed)
__device__ float g_Ha[BATCH * HSIZE];
__device__ float g_Hb[BATCH * HSIZE];
__device__ int   g_jtab[NOUT];       // packed (level<<20)|word_index, in output order
__device__ int   g_blockcnt[NBLK_LYN];
__device__ int   g_blockoff[NBLK_LYN];

// ---------------------------------------------------------------------------
// Lyndon word machinery: w (length k, base-8 digits, MSD first) is Lyndon iff
// it is strictly smaller than every proper rotation.
// ---------------------------------------------------------------------------
__device__ __forceinline__ bool is_lyndon(unsigned w, int k) {
    #pragma unroll
    for (int r = 1; r < 6; r++) {
        if (r >= k) break;
        int sh = 3 * (k - r);
        unsigned rot = ((w & ((1u << sh) - 1u)) << (3 * r)) | (w >> sh);
        if (rot <= w) return false;
    }
    return true;
}

__device__ __forceinline__ void lyn_block_decode(int bb, int& level, int& tile) {
    if (bb < 4)       { level = bb + 1; tile = 0; }
    else if (bb < 12) { level = 5;      tile = bb - 4; }
    else              { level = 6;      tile = bb - 12; }
}

// Pass 1: per-block Lyndon counts (512 thr x 8 items = 4096 words/block)
__global__ void __launch_bounds__(512) lyndon_count_kernel() {
    int level, tile;
    lyn_block_decode(blockIdx.x, level, tile);
    int lsz  = 1 << (3 * level);
    int base = tile * 4096 + threadIdx.x * 8;
    int cnt  = 0;
    #pragma unroll
    for (int t = 0; t < 8; t++) {
        int w = base + t;
        if (w < lsz && is_lyndon((unsigned)w, level)) cnt++;
    }
    __shared__ int s[512];
    s[threadIdx.x] = cnt;
    __syncthreads();
    for (int o = 256; o > 0; o >>= 1) {
        if (threadIdx.x < o) s[threadIdx.x] += s[threadIdx.x + o];
        __syncthreads();
    }
    if (threadIdx.x == 0) g_blockcnt[blockIdx.x] = s[0];
}

// Pass 2: exclusive scan of the 76 block counts (block order == output order)
__global__ void __launch_bounds__(128) lyndon_scan_kernel() {
    __shared__ int s[128];
    int tid = threadIdx.x;
    int v = (tid < NBLK_LYN) ? g_blockcnt[tid] : 0;
    s[tid] = v;
    __syncthreads();
    for (int off = 1; off < 128; off <<= 1) {
        int t = s[tid];
        if (tid >= off) t += s[tid - off];
        __syncthreads();
        s[tid] = t;
        __syncthreads();
    }
    if (tid < NBLK_LYN) g_blockoff[tid] = s[tid] - v;   // exclusive
}

// Pass 3: compact word indices into g_jtab in output order
__global__ void __launch_bounds__(512) lyndon_fill_kernel() {
    int level, tile;
    lyn_block_decode(blockIdx.x, level, tile);
    int lsz  = 1 << (3 * level);
    int base = tile * 4096 + threadIdx.x * 8;
    int flags = 0, cnt = 0;
    #pragma unroll
    for (int t = 0; t < 8; t++) {
        int w = base + t;
        if (w < lsz && is_lyndon((unsigned)w, level)) { flags |= 1 << t; cnt++; }
    }
    __shared__ int s[512];
    s[threadIdx.x] = cnt;
    __syncthreads();
    for (int off = 1; off < 512; off <<= 1) {
        int t = s[threadIdx.x];
        if (threadIdx.x >= off) t += s[threadIdx.x - off];
        __syncthreads();
        s[threadIdx.x] = t;
        __syncthreads();
    }
    int j = g_blockoff[blockIdx.x] + (s[threadIdx.x] - cnt);
    #pragma unroll
    for (int t = 0; t < 8; t++) {
        if ((flags >> t) & 1) g_jtab[j++] = (level << 20) | (base + t);
    }
}

// ---------------------------------------------------------------------------
// Horner step: Hnew = (nonconst part of) x (tensor) (c_old + Hold),
// storing only levels 1..s. Entry e in [0,S) is (level k, word widx),
// e == OFF[k] + widx.
// Hnew_k[w] = c_old * x_k[w] + sum_{i=1}^{k-1} x_i[prefix_i(w)] * Hold_{k-i}[suffix(w)]
// ---------------------------------------------------------------------------
__global__ void __launch_bounds__(256) horner_step_kernel(
        const float* __restrict__ sig, int S, float c_old, int src_sel) {
    int e = blockIdx.x * blockDim.x + threadIdx.x;
    if (e >= S) return;
    int b = blockIdx.y;

    const float* Hold = src_sel ? g_Ha : g_Hb;
    float*       Hnew = src_sel ? g_Hb : g_Ha;

    int k = (e < 8) ? 1 : (e < 72) ? 2 : (e < 584) ? 3 : (e < 4680) ? 4 : 5;
    int widx = e - d_OFF[k];

    const float* xr = sig + (size_t)b * SIG_SIZE;
    const float* hr = Hold + (size_t)b * HSIZE;

    float v = __ldg(&xr[e]) * c_old;
    for (int i = 1; i < k; i++) {
        int sh = 3 * (k - i);
        v += __ldg(&xr[d_OFF[i] + (widx >> sh)]) *
             __ldg(&hr[d_OFF[k - i] + (widx & ((1 << sh) - 1))]);
    }
    Hnew[(size_t)b * HSIZE + e] = v;
}

// ---------------------------------------------------------------------------
// Main: out[b][j] = (x tensor (1 + H5))[word(j)].
// ---------------------------------------------------------------------------
__global__ void __launch_bounds__(256) logsig_main_kernel(
        const float* __restrict__ sig, float* __restrict__ out) {
    int j = blockIdx.x * blockDim.x + threadIdx.x;
    if (j >= NOUT) return;
    int b = blockIdx.y;

    int packed = __ldg(&g_jtab[j]);
    int k    = packed >> 20;
    int widx = packed & 0xFFFFF;

    const float* xr = sig + (size_t)b * SIG_SIZE;
    const float* hr = g_Ha + (size_t)b * HSIZE;   // H5 lives in buffer A after step 5

    float v;
    if (k == 6) {
        v  = __ldg(&xr[37448 + widx]);
        v += __ldg(&xr[0    + (widx >> 15)]) * __ldg(&hr[4680 + (widx & 0x7FFF)]);
        v += __ldg(&xr[8    + (widx >> 12)]) * __ldg(&hr[584  + (widx & 0xFFF)]);
        v += __ldg(&xr[72   + (widx >> 9) ]) * __ldg(&hr[72   + (widx & 0x1FF)]);
        v += __ldg(&xr[584  + (widx >> 6) ]) * __ldg(&hr[8    + (widx & 0x3F)]);
        v += __ldg(&xr[4680 + (widx >> 3) ]) * __ldg(&hr[0    + (widx & 0x7)]);
    } else {
        v = __ldg(&xr[d_OFF[k] + widx]);
        for (int i = 1; i < k; i++) {
            int sh = 3 * (k - i);
            v += __ldg(&xr[d_OFF[i] + (widx >> sh)]) *
                 __ldg(&hr[d_OFF[k - i] + (widx & ((1 << sh) - 1))]);
        }
    }
    out[(size_t)b * NOUT + j] = v;
}

// ---------------------------------------------------------------------------
extern "C" void kernel_launch(void* const* d_in, const int* in_sizes, int n_in,
                              void* d_out, int out_size) {
    (void)in_sizes; (void)n_in; (void)out_size;
    const float* sig = (const float*)d_in[0];
    float* out = (float*)d_out;

    // Build Lyndon index table (rebuilt every call — deterministic, cheap)
    lyndon_count_kernel<<<NBLK_LYN, 512>>>();
    lyndon_scan_kernel<<<1, 128>>>();
    lyndon_fill_kernel<<<NBLK_LYN, 512>>>();

    // Horner: Q5 = -1/6; Q_{s} = c + x*Q_{s+1}. H buffers alternate A,B,A,B,A.
    {
        dim3 g1((8     + 255) / 256, BATCH); horner_step_kernel<<<g1, 256>>>(sig, 8,     -1.0f/6.0f, 0); // ->A
        dim3 g2((72    + 255) / 256, BATCH); horner_step_kernel<<<g2, 256>>>(sig, 72,     1.0f/5.0f, 1); // A->B
        dim3 g3((584   + 255) / 256, BATCH); horner_step_kernel<<<g3, 256>>>(sig, 584,   -1.0f/4.0f, 0); // B->A
        dim3 g4((4680  + 255) / 256, BATCH); horner_step_kernel<<<g4, 256>>>(sig, 4680,   1.0f/3.0f, 1); // A->B
        dim3 g5((HSIZE + 255) / 256, BATCH); horner_step_kernel<<<g5, 256>>>(sig, HSIZE, -1.0f/2.0f, 0); // B->A
    }

    // Final fused product + Lyndon gather
    dim3 gm((NOUT + 255) / 256, BATCH);
    logsig_main_kernel<<<gm, 256>>>(sig, out);
}